// round 2
// baseline (speedup 1.0000x reference)
#include <cuda_runtime.h>
#include <math.h>

// Problem constants
#define NN 64
#define TT 512
#define VV 25
#define CIN 3
#define CH 64
#define FF 25
#define GG 100   // 4*F

typedef unsigned long long ull;

// ---------------- scratch (device globals: no allocation allowed) ----------------
__device__ float g_x1[(size_t)NN * TT * VV * CH];   // (N,T,V,CH)      210 MB
__device__ float g_zx[(size_t)TT * NN * VV * GG];   // (T,N,V,4F)      327 MB
__device__ float g_f1[(size_t)NN * TT * VV * FF];   // (N,T,V,F)        82 MB

// ---------------- f32x2 packed helpers ----------------
__device__ __forceinline__ ull splat2(float v) {
    ull r; asm("mov.b64 %0, {%1, %1};" : "=l"(r) : "f"(v)); return r;
}
__device__ __forceinline__ ull pack2(float lo, float hi) {
    ull r; asm("mov.b64 %0, {%1, %2};" : "=l"(r) : "f"(lo), "f"(hi)); return r;
}
__device__ __forceinline__ void unpack2(ull p, float& lo, float& hi) {
    asm("mov.b64 {%0, %1}, %2;" : "=f"(lo), "=f"(hi) : "l"(p));
}
__device__ __forceinline__ ull fma2(ull a, ull b, ull c) {
    ull d; asm("fma.rn.f32x2 %0, %1, %2, %3;" : "=l"(d) : "l"(a), "l"(b), "l"(c)); return d;
}
__device__ __forceinline__ float hsig(float x) {  // Keras hard_sigmoid
    return __saturatef(fmaf(0.2f, x, 0.5f));
}

// =====================================================================
// Kernel A: x1 = relu(x @ W_conv + b_conv); zx = x1 @ W_lstm + b_lstm
// grid (T/16, N), 256 threads. Processes 16 timesteps per block in
// sub-chunks of 2 timesteps (50 positions), W_lstm staged in smem once.
// =====================================================================
#define TB 16
__global__ __launch_bounds__(256) void kA(const float* __restrict__ x,
                                          const float* __restrict__ Wc,
                                          const float* __restrict__ bc,
                                          const float* __restrict__ Wl,
                                          const float* __restrict__ bl)
{
    __shared__ float sWc[CIN * CH];
    __shared__ float sbc[CH];
    __shared__ __align__(16) float sbl[GG];
    __shared__ __align__(16) float sWl[CH * GG];   // 25.6 KB
    __shared__ float sx1[50][CH];                  // 12.8 KB (2 timesteps)

    const int tid = threadIdx.x;
    const int n   = blockIdx.y;
    const int t0  = blockIdx.x * TB;

    for (int i = tid; i < CIN * CH; i += 256) sWc[i] = Wc[i];
    if (tid < CH) sbc[tid] = bc[tid];
    if (tid < GG) sbl[tid] = bl[tid];
    for (int i = tid; i < CH * GG; i += 256) sWl[i] = Wl[i];
    __syncthreads();

    for (int sub = 0; sub < TB; sub += 2) {
        const int tb = t0 + sub;
        // ---- phase A: x1 for 50 positions (2 timesteps x 25 joints) ----
        for (int idx = tid; idx < 50 * CH; idx += 256) {
            int p = idx >> 6, c = idx & 63;
            int dt = p / 25, v = p - dt * 25;
            size_t pos = ((size_t)n * TT + (tb + dt)) * VV + v;
            const float* xp = x + pos * CIN;
            float a = fmaf(xp[0], sWc[c],
                      fmaf(xp[1], sWc[CH + c],
                      fmaf(xp[2], sWc[2 * CH + c], sbc[c])));
            a = fmaxf(a, 0.f);
            sx1[p][c] = a;
            g_x1[pos * CH + c] = a;
        }
        __syncthreads();
        // ---- phase B: z = x1 @ W_lstm + b (f32x2 packed, 4 gates/thread) ----
        for (int idx = tid; idx < 50 * 25; idx += 256) {
            int p = idx / 25, q = idx - 25 * p;   // gates 4q..4q+3
            int dt = p / 25, v = p - dt * 25;
            const ulonglong2 b2 = *reinterpret_cast<const ulonglong2*>(&sbl[4 * q]);
            ull acc0 = b2.x, acc1 = b2.y;
            const float* xr = sx1[p];
            #pragma unroll
            for (int k = 0; k < CH; k++) {
                ull a = splat2(xr[k]);
                const ulonglong2 w = *reinterpret_cast<const ulonglong2*>(&sWl[k * GG + 4 * q]);
                acc0 = fma2(a, w.x, acc0);
                acc1 = fma2(a, w.y, acc1);
            }
            size_t zpos = (((size_t)(tb + dt) * NN + n) * VV + v) * GG + 4 * q;
            *reinterpret_cast<ulonglong2*>(&g_zx[zpos]) = make_ulonglong2(acc0, acc1);
        }
        __syncthreads();
    }
}

// =====================================================================
// Kernel B: per-(n,v) LSTM over T=512, ONE WARP per sequence.
// Lane q (0..24) owns gates {q, q+25, q+50, q+75}; U columns pre-packed
// into f32x2 pairs in registers. h propagates via warp shuffles only —
// zero shared memory, zero barriers in the 512-step loop.
// grid = 400 blocks x 128 threads (4 warps = 4 sequences per block).
// =====================================================================
__global__ __launch_bounds__(128) void kB(const float* __restrict__ U)
{
    const int warp = threadIdx.x >> 5;
    const int lane = threadIdx.x & 31;
    const int seq  = blockIdx.x * 4 + warp;     // 0..1599
    const int n = seq / VV;
    const int v = seq - n * VV;
    const int q = (lane < FF) ? lane : 0;       // clamp idle lanes

    // Pre-pack U columns: wif[k] = {U[k][q], U[k][q+25]}, wco[k] = {U[k][q+50], U[k][q+75]}
    ull wif[FF], wco[FF];
    #pragma unroll
    for (int k = 0; k < FF; k++) {
        const float* ur = U + k * GG;
        wif[k] = pack2(ur[q], ur[q + FF]);
        wco[k] = pack2(ur[q + 2 * FF], ur[q + 3 * FF]);
    }

    const float* zrow = g_zx + ((size_t)n * VV + v) * GG;   // + t*zstride
    const size_t zstride = (size_t)NN * VV * GG;            // 160000
    float* f1p = g_f1 + (((size_t)n * TT) * VV + v) * FF + q;
    const size_t f1stride = (size_t)VV * FF;                // 625

    float h = 0.f, c = 0.f;

    // prefetch z for t=0
    ull zif = pack2(zrow[q],          zrow[q + FF]);
    ull zco = pack2(zrow[q + 2 * FF], zrow[q + 3 * FF]);

    for (int t = 0; t < TT; t++) {
        // prefetch next step's z
        ull zif_n = 0ull, zco_n = 0ull;
        if (t + 1 < TT) {
            const float* zn = zrow + (size_t)(t + 1) * zstride;
            zif_n = pack2(zn[q],          zn[q + FF]);
            zco_n = pack2(zn[q + 2 * FF], zn[q + 3 * FF]);
        }
        // gates = z + h @ U, all-shuffle broadcast of h
        ull aif = zif, aco = zco;
        #pragma unroll
        for (int k = 0; k < FF; k++) {
            float hk = __shfl_sync(0xffffffffu, h, k);
            ull a = splat2(hk);
            aif = fma2(a, wif[k], aif);
            aco = fma2(a, wco[k], aco);
        }
        float i_, f_, g_, o_;
        unpack2(aif, i_, f_);
        unpack2(aco, g_, o_);
        c = hsig(f_) * c + hsig(i_) * tanhf(g_);
        h = hsig(o_) * tanhf(c);
        if (lane < FF) f1p[(size_t)t * f1stride] = h;
        zif = zif_n; zco = zco_n;
    }
}

// =====================================================================
// Kernel C: coefs = softmax(leaky_relu(f1) + bias_mat, axis=-1);
//           out = coefs @ x1.   One block per (n,t), 256 threads.
// =====================================================================
__global__ __launch_bounds__(256) void kC(const float* __restrict__ bias,
                                          float* __restrict__ out)
{
    __shared__ float sc[VV][VV + 1];                 // coefs (padded)
    __shared__ __align__(16) float sx[VV][CH];       // x1 tile

    const int tid = threadIdx.x;
    const size_t nt = (size_t)blockIdx.y * TT + blockIdx.x;
    const float* f1p = g_f1 + nt * (VV * FF);
    const float* x1p = g_x1 + nt * (VV * CH);

    for (int i = tid; i < VV * FF; i += 256) {
        float val = f1p[i];
        val = (val > 0.f) ? val : 0.2f * val;        // leaky_relu alpha=0.2
        int v = i / FF, w = i - FF * v;
        sc[v][w] = val + bias[i];                    // bias_mat[v][w]
    }
    for (int i = tid; i < VV * CH; i += 256) sx[i >> 6][i & 63] = x1p[i];
    __syncthreads();

    if (tid < VV) {                                  // row-wise softmax
        float m = -1e30f;
        #pragma unroll
        for (int w = 0; w < VV; w++) m = fmaxf(m, sc[tid][w]);
        float s = 0.f;
        #pragma unroll
        for (int w = 0; w < VV; w++) { float e = expf(sc[tid][w] - m); sc[tid][w] = e; s += e; }
        float inv = 1.f / s;
        #pragma unroll
        for (int w = 0; w < VV; w++) sc[tid][w] *= inv;
    }
    __syncthreads();

    // out[v][c..c+3] per thread via f32x2
    for (int idx = tid; idx < VV * 16; idx += 256) {
        int v = idx >> 4, cq = idx & 15;             // c = 4*cq
        ull acc0 = 0ull, acc1 = 0ull;
        #pragma unroll
        for (int w = 0; w < VV; w++) {
            ull a = splat2(sc[v][w]);
            const ulonglong2 xw = *reinterpret_cast<const ulonglong2*>(&sx[w][4 * cq]);
            acc0 = fma2(a, xw.x, acc0);
            acc1 = fma2(a, xw.y, acc1);
        }
        *reinterpret_cast<ulonglong2*>(&out[nt * (VV * CH) + v * CH + 4 * cq]) =
            make_ulonglong2(acc0, acc1);
    }
}

// =====================================================================
extern "C" void kernel_launch(void* const* d_in, const int* in_sizes, int n_in,
                              void* d_out, int out_size)
{
    const float* x    = (const float*)d_in[0];  // (N,T,V,CIN)
    const float* Wc   = (const float*)d_in[1];  // (CIN,CH)
    const float* bc   = (const float*)d_in[2];  // (CH,)
    const float* Wl   = (const float*)d_in[3];  // (CH,4F)
    const float* Ul   = (const float*)d_in[4];  // (F,4F)
    const float* bl   = (const float*)d_in[5];  // (4F,)
    const float* bias = (const float*)d_in[6];  // (V,V)
    float* out = (float*)d_out;                 // (N,T,V,CH)

    kA<<<dim3(TT / TB, NN), 256>>>(x, Wc, bc, Wl, bl);
    kB<<<400, 128>>>(Ul);
    kC<<<dim3(TT, NN), 256>>>(bias, out);
}

// round 4
// speedup vs baseline: 1.7186x; 1.7186x over previous
#include <cuda_runtime.h>
#include <math.h>

// Problem constants
#define NN 64
#define TT 512
#define VV 25
#define CIN 3
#define CH 64
#define FF 25
#define GG 100   // 4*F

typedef unsigned long long ull;

// ---------------- scratch (device globals: no allocation allowed) ----------------
__device__ float g_x1[(size_t)NN * TT * VV * CH];   // (N,T,V,CH)
__device__ float g_zx[(size_t)TT * NN * VV * GG];   // (T,N,V,4F)
__device__ float g_f1[(size_t)NN * TT * VV * FF];   // (N,T,V,F)

// ---------------- f32x2 packed helpers ----------------
__device__ __forceinline__ ull splat2(float v) {
    ull r; asm("mov.b64 %0, {%1, %1};" : "=l"(r) : "f"(v)); return r;
}
__device__ __forceinline__ ull pack2(float lo, float hi) {
    ull r; asm("mov.b64 %0, {%1, %2};" : "=l"(r) : "f"(lo), "f"(hi)); return r;
}
__device__ __forceinline__ void unpack2(ull p, float& lo, float& hi) {
    asm("mov.b64 {%0, %1}, %2;" : "=f"(lo), "=f"(hi) : "l"(p));
}
__device__ __forceinline__ ull fma2(ull a, ull b, ull c) {
    ull d; asm("fma.rn.f32x2 %0, %1, %2, %3;" : "=l"(d) : "l"(a), "l"(b), "l"(c)); return d;
}
__device__ __forceinline__ float hsig(float x) {  // Keras hard_sigmoid
    return __saturatef(fmaf(0.2f, x, 0.5f));
}
// fast tanh: clamp then (e^{2x}-1)/(e^{2x}+1); safe for |x| large (no inf/inf)
__device__ __forceinline__ float ftanh(float x) {
    float a = fminf(fabsf(x), 15.f);
    float e = __expf(2.f * a);
    float r = __fdividef(e - 1.f, e + 1.f);
    return copysignf(r, x);
}

// =====================================================================
// Kernel A: x1 = relu(x @ W_conv + b_conv); zx = x1 @ W_lstm + b_lstm
// grid (T/16, N), 256 threads, dynamic smem (~54KB).
// 4-timestep chunks (100 positions). Phase B register-blocked:
// thread (q,pg) computes gates 4q..4q+3 for 10 positions -> per k:
// 1 LDS.128 (w) + 10 broadcast LDS.32 (x) feed 20 FMA2.
// =====================================================================
#define TB 16
#define CT 4          // timesteps per chunk
#define PCH (CT*VV)   // 100 positions per chunk

// dynamic smem layout (floats)
#define S_WL   0                      // 6400  : W_lstm (64 x 100)
#define S_X1   (S_WL + CH*GG)         // 6400  : x1 tile (100 x 64)
#define S_WC   (S_X1 + PCH*CH)        // 192
#define S_BC   (S_WC + CIN*CH)        // 64
#define S_BL   (S_BC + CH)            // 100
#define S_XIN  (S_BL + GG)            // 300
#define S_TOT  (S_XIN + PCH*CIN)      // 13456 floats = 53824 B

__global__ __launch_bounds__(256) void kA(const float* __restrict__ x,
                                          const float* __restrict__ Wc,
                                          const float* __restrict__ bc,
                                          const float* __restrict__ Wl,
                                          const float* __restrict__ bl)
{
    extern __shared__ __align__(16) float sm[];
    float* sWl  = sm + S_WL;
    float* sx1  = sm + S_X1;
    float* sWc  = sm + S_WC;
    float* sbc  = sm + S_BC;
    float* sbl  = sm + S_BL;
    float* sxin = sm + S_XIN;

    const int tid = threadIdx.x;
    const int n   = blockIdx.y;
    const int t0  = blockIdx.x * TB;

    for (int i = tid; i < CIN * CH; i += 256) sWc[i] = Wc[i];
    if (tid < CH) sbc[tid] = bc[tid];
    if (tid < GG) sbl[tid] = bl[tid];
    for (int i = tid; i < CH * GG; i += 256) sWl[i] = Wl[i];

    const int pg = tid / 25;          // 0..9 (tid<250)
    const int q  = tid - pg * 25;     // 0..24

    for (int tb = t0; tb < t0 + TB; tb += CT) {
        // ---- stage raw x chunk (300 floats, contiguous) ----
        const float* xsrc = x + (((size_t)n * TT + tb) * VV) * CIN;
        for (int i = tid; i < PCH * CIN; i += 256) sxin[i] = xsrc[i];
        __syncthreads();   // staging visible AND previous phase-B done

        // ---- phase A: x1 for 100 positions ----
        float* x1dst = g_x1 + (((size_t)n * TT + tb) * VV) * CH;
        for (int idx = tid; idx < PCH * CH; idx += 256) {
            int p = idx >> 6, c = idx & 63;
            const float* xi = &sxin[3 * p];
            float a = fmaf(xi[0], sWc[c],
                      fmaf(xi[1], sWc[CH + c],
                      fmaf(xi[2], sWc[2 * CH + c], sbc[c])));
            a = fmaxf(a, 0.f);
            sx1[p * CH + c] = a;
            x1dst[idx] = a;
        }
        __syncthreads();

        // ---- phase B: z = x1 @ W_lstm + b, register-blocked ----
        if (tid < 250) {
            ull acc[20];
            const ulonglong2 b2 = *reinterpret_cast<const ulonglong2*>(&sbl[4 * q]);
            #pragma unroll
            for (int i = 0; i < 10; i++) { acc[2 * i] = b2.x; acc[2 * i + 1] = b2.y; }

            const float* xb = &sx1[(pg * 10) * CH];
            const float* wb = &sWl[4 * q];
            #pragma unroll 4
            for (int k = 0; k < CH; k++) {
                const ulonglong2 w = *reinterpret_cast<const ulonglong2*>(&wb[k * GG]);
                #pragma unroll
                for (int i = 0; i < 10; i++) {
                    ull a = splat2(xb[i * CH + k]);
                    acc[2 * i]     = fma2(a, w.x, acc[2 * i]);
                    acc[2 * i + 1] = fma2(a, w.y, acc[2 * i + 1]);
                }
            }
            #pragma unroll
            for (int i = 0; i < 10; i++) {
                int p  = pg * 10 + i;
                int dt = p / 25, v = p - dt * 25;
                size_t zpos = (((size_t)(tb + dt) * NN + n) * VV + v) * GG + 4 * q;
                *reinterpret_cast<ulonglong2*>(&g_zx[zpos]) =
                    make_ulonglong2(acc[2 * i], acc[2 * i + 1]);
            }
        }
        __syncthreads();
    }
}

// =====================================================================
// Kernel B: per-(n,v) LSTM over T=512, ONE WARP per sequence.
// Lane q owns gates {q, q+25, q+50, q+75}; U columns packed as f32x2 in
// registers; h broadcast via shuffles; zero barriers in the loop.
// z prefetched 3 steps deep to cover DRAM latency.
// =====================================================================
__global__ __launch_bounds__(128) void kB(const float* __restrict__ U)
{
    const int warp = threadIdx.x >> 5;
    const int lane = threadIdx.x & 31;
    const int seq  = blockIdx.x * 4 + warp;     // 0..1599
    const int n = seq / VV;
    const int v = seq - n * VV;
    const int q = (lane < FF) ? lane : 0;       // clamp idle lanes

    ull wif[FF], wco[FF];
    #pragma unroll
    for (int k = 0; k < FF; k++) {
        const float* ur = U + k * GG;
        wif[k] = pack2(ur[q], ur[q + FF]);
        wco[k] = pack2(ur[q + 2 * FF], ur[q + 3 * FF]);
    }

    const float* zrow = g_zx + ((size_t)n * VV + v) * GG;
    const size_t zstride = (size_t)NN * VV * GG;   // 160000
    float* f1p = g_f1 + (((size_t)n * TT) * VV + v) * FF + q;
    const size_t f1stride = (size_t)VV * FF;       // 625

    float h = 0.f, c = 0.f;

    // 3-deep prefetch pipeline (stages hold raw floats; pack at consume)
    float s0i, s0f, s0g, s0o, s1i, s1f, s1g, s1o, s2i, s2f, s2g, s2o;
    {
        const float* z0 = zrow;
        const float* z1 = zrow + zstride;
        const float* z2 = zrow + 2 * zstride;
        s0i = z0[q]; s0f = z0[q + FF]; s0g = z0[q + 2 * FF]; s0o = z0[q + 3 * FF];
        s1i = z1[q]; s1f = z1[q + FF]; s1g = z1[q + 2 * FF]; s1o = z1[q + 3 * FF];
        s2i = z2[q]; s2f = z2[q + FF]; s2g = z2[q + 2 * FF]; s2o = z2[q + 3 * FF];
    }

    for (int t = 0; t < TT; t++) {
        float ni = 0.f, nf = 0.f, ng = 0.f, no = 0.f;
        if (t + 3 < TT) {
            const float* zn = zrow + (size_t)(t + 3) * zstride;
            ni = zn[q]; nf = zn[q + FF]; ng = zn[q + 2 * FF]; no = zn[q + 3 * FF];
        }
        ull aif = pack2(s0i, s0f);
        ull aco = pack2(s0g, s0o);
        #pragma unroll
        for (int k = 0; k < FF; k++) {
            float hk = __shfl_sync(0xffffffffu, h, k);
            ull a = splat2(hk);
            aif = fma2(a, wif[k], aif);
            aco = fma2(a, wco[k], aco);
        }
        float i_, f_, g_, o_;
        unpack2(aif, i_, f_);
        unpack2(aco, g_, o_);
        c = hsig(f_) * c + hsig(i_) * ftanh(g_);
        h = hsig(o_) * ftanh(c);
        if (lane < FF) f1p[(size_t)t * f1stride] = h;
        s0i = s1i; s0f = s1f; s0g = s1g; s0o = s1o;
        s1i = s2i; s1f = s2f; s1g = s2g; s1o = s2o;
        s2i = ni;  s2f = nf;  s2g = ng;  s2o = no;
    }
}

// =====================================================================
// Kernel C: coefs = softmax(leaky_relu(f1) + bias_mat, axis=-1);
//           out = coefs @ x1.   One block per (n,t), 256 threads.
// Aggregation: thread (v,cg) computes 8 channels; per k:
// 1 broadcast LDS + 2 LDS.128 feed 4 FMA2.
// =====================================================================
__global__ __launch_bounds__(256) void kC(const float* __restrict__ bias,
                                          float* __restrict__ out)
{
    __shared__ float sc[VV][VV + 1];                 // coefs (padded)
    __shared__ __align__(16) float sx[VV][CH];       // x1 tile

    const int tid = threadIdx.x;
    const size_t nt = (size_t)blockIdx.y * TT + blockIdx.x;
    const float* f1p = g_f1 + nt * (VV * FF);
    const float* x1p = g_x1 + nt * (VV * CH);

    for (int i = tid; i < VV * FF; i += 256) {
        float val = f1p[i];
        val = (val > 0.f) ? val : 0.2f * val;        // leaky_relu alpha=0.2
        int v = i / FF, w = i - FF * v;
        sc[v][w] = val + bias[i];
    }
    for (int i = tid; i < VV * CH; i += 256) sx[i >> 6][i & 63] = x1p[i];
    __syncthreads();

    if (tid < VV) {                                  // row-wise softmax
        float m = -1e30f;
        #pragma unroll
        for (int w = 0; w < VV; w++) m = fmaxf(m, sc[tid][w]);
        float s = 0.f;
        #pragma unroll
        for (int w = 0; w < VV; w++) { float e = expf(sc[tid][w] - m); sc[tid][w] = e; s += e; }
        float inv = 1.f / s;
        #pragma unroll
        for (int w = 0; w < VV; w++) sc[tid][w] *= inv;
    }
    __syncthreads();

    if (tid < 200) {
        int v = tid >> 3, cg = tid & 7;              // channels 8*cg .. 8*cg+7
        ull a0 = 0ull, a1 = 0ull, a2 = 0ull, a3 = 0ull;
        #pragma unroll
        for (int w = 0; w < VV; w++) {
            ull a = splat2(sc[v][w]);
            const ulonglong2* xr = reinterpret_cast<const ulonglong2*>(&sx[w][8 * cg]);
            ulonglong2 xv0 = xr[0];
            ulonglong2 xv1 = xr[1];
            a0 = fma2(a, xv0.x, a0);
            a1 = fma2(a, xv0.y, a1);
            a2 = fma2(a, xv1.x, a2);
            a3 = fma2(a, xv1.y, a3);
        }
        float* op = &out[nt * (VV * CH) + v * CH + 8 * cg];
        reinterpret_cast<ulonglong2*>(op)[0] = make_ulonglong2(a0, a1);
        reinterpret_cast<ulonglong2*>(op)[1] = make_ulonglong2(a2, a3);
    }
}

// =====================================================================
extern "C" void kernel_launch(void* const* d_in, const int* in_sizes, int n_in,
                              void* d_out, int out_size)
{
    const float* x    = (const float*)d_in[0];  // (N,T,V,CIN)
    const float* Wc   = (const float*)d_in[1];  // (CIN,CH)
    const float* bc   = (const float*)d_in[2];  // (CH,)
    const float* Wl   = (const float*)d_in[3];  // (CH,4F)
    const float* Ul   = (const float*)d_in[4];  // (F,4F)
    const float* bl   = (const float*)d_in[5];  // (4F,)
    const float* bias = (const float*)d_in[6];  // (V,V)
    float* out = (float*)d_out;                 // (N,T,V,CH)

    cudaFuncSetAttribute(kA, cudaFuncAttributeMaxDynamicSharedMemorySize,
                         (int)(S_TOT * sizeof(float)));
    kA<<<dim3(TT / TB, NN), 256, S_TOT * sizeof(float)>>>(x, Wc, bc, Wl, bl);
    kB<<<400, 128>>>(Ul);
    kC<<<dim3(TT, NN), 256>>>(bias, out);
}